// round 2
// baseline (speedup 1.0000x reference)
#include <cuda_runtime.h>

#define NB 32768
#define NL 1024
#define NK 5
#define FEA 1028
#define MD 50
#define DD 32
#define SHRINKF 0.0025f
#define EPSF 1e-12f

// Scratch (__device__ globals; no allocation allowed)
__device__ float  g_M2[MD * NL];          // conv-folded mem_W (k-major), 200 KB
__device__ float2 g_attT[MD * NB];        // att, k-major, value DUPLICATED in float2: 13.1 MB

// ---------------------------------------------------------------------------
// f32x2 helpers
// ---------------------------------------------------------------------------
__device__ __forceinline__ void fma2(unsigned long long& d,
                                     unsigned long long a,
                                     unsigned long long b) {
    asm("fma.rn.f32x2 %0, %1, %2, %0;" : "+l"(d) : "l"(a), "l"(b));
}
__device__ __forceinline__ float2 unpk(unsigned long long v) {
    float2 r;
    asm("mov.b64 {%0, %1}, %2;" : "=f"(r.x), "=f"(r.y) : "l"(v));
    return r;
}

// ---------------------------------------------------------------------------
// Kernel 1: fold transposed conv into mem_W.  M2[d][i] = sum_k mem_W[d][i+k]*convt_w[4-k]
// ---------------------------------------------------------------------------
__global__ void k_prep_m2(const float* __restrict__ mem_W,
                          const float* __restrict__ convt_w) {
    int idx = blockIdx.x * blockDim.x + threadIdx.x;
    if (idx >= MD * NL) return;
    int d = idx / NL, i = idx - d * NL;
    float s = 0.f;
#pragma unroll
    for (int k = 0; k < NK; k++)
        s += mem_W[d * FEA + i + k] * convt_w[NK - 1 - k];
    g_M2[idx] = s;
}

// ---------------------------------------------------------------------------
// Kernel 2: att per row, one thread per row. Writes k-major, duplicated float2.
// ---------------------------------------------------------------------------
__global__ __launch_bounds__(128) void k_att(const float* __restrict__ date_vec,
                                             const float* __restrict__ date_W) {
    __shared__ float dW[MD * DD];
    int tid = threadIdx.x;
    for (int i = tid; i < MD * DD; i += 128) dW[i] = date_W[i];
    __syncthreads();

    int b = blockIdx.x * 128 + tid;
    float4 dv[8];
    const float4* dvp = (const float4*)(date_vec + (size_t)b * DD);
#pragma unroll
    for (int i = 0; i < 8; i++) dv[i] = dvp[i];

    float s[MD];
#pragma unroll
    for (int j = 0; j < MD; j++) {
        const float4* w4 = (const float4*)(dW + j * DD);  // broadcast reads
        float acc = 0.f;
#pragma unroll
        for (int i = 0; i < 8; i++) {
            float4 w = w4[i];
            acc += dv[i].x * w.x + dv[i].y * w.y + dv[i].z * w.z + dv[i].w * w.w;
        }
        s[j] = acc;
    }
    float m = -1e30f;
#pragma unroll
    for (int j = 0; j < MD; j++) m = fmaxf(m, s[j]);
    float sum = 0.f;
#pragma unroll
    for (int j = 0; j < MD; j++) { s[j] = expf(s[j] - m); sum += s[j]; }
    float inv = 1.f / sum;
    float sa = 0.f;
#pragma unroll
    for (int j = 0; j < MD; j++) {
        float a = s[j] * inv;
        float t = a - SHRINKF;
        float v = fmaxf(t, 0.f) * a / (fabsf(t) + EPSF);
        s[j] = v;
        sa += v;             // v >= 0 always
    }
    float inv2 = 1.f / (sa + EPSF);
#pragma unroll
    for (int j = 0; j < MD; j++) {
        float v = s[j] * inv2;
        g_attT[(size_t)j * NB + b] = make_float2(v, v);   // coalesced per j
    }
}

// ---------------------------------------------------------------------------
// Kernel 3: weight/bias per row (streams x, 128 MB). Writes into d_out tail.
// ---------------------------------------------------------------------------
__global__ __launch_bounds__(256) void k_wb(const float* __restrict__ x,
                                            const float* __restrict__ fcw_w,
                                            const float* __restrict__ fcw_b,
                                            const float* __restrict__ fcb_w,
                                            const float* __restrict__ fcb_b,
                                            float* __restrict__ out) {
    __shared__ float4 wS[256], bS[256];
    int tid = threadIdx.x;
    wS[tid] = ((const float4*)fcw_w)[tid];
    bS[tid] = ((const float4*)fcb_w)[tid];
    __syncthreads();

    int w = tid >> 5, l = tid & 31;
    int b = blockIdx.x * 8 + w;
    const float4* xr = (const float4*)(x + (size_t)b * NL);
    float wa = 0.f, ba = 0.f;
#pragma unroll
    for (int i = 0; i < 8; i++) {
        float4 xv = xr[i * 32 + l];
        float4 fw = wS[i * 32 + l];
        float4 fb = bS[i * 32 + l];
        wa += xv.x * fw.x + xv.y * fw.y + xv.z * fw.z + xv.w * fw.w;
        ba += xv.x * fb.x + xv.y * fb.y + xv.z * fb.z + xv.w * fb.w;
    }
#pragma unroll
    for (int o = 16; o; o >>= 1) {
        wa += __shfl_xor_sync(~0u, wa, o);
        ba += __shfl_xor_sync(~0u, ba, o);
    }
    if (l == 0) {
        out[(size_t)NB * NL + b]      = tanhf(wa + fcw_b[0]) * 0.5f + 1.0f;
        out[(size_t)NB * NL + NB + b] = tanhf(ba + fcb_b[0]) * 0.5f;
    }
}

// ---------------------------------------------------------------------------
// Kernel 4: GEMM  out[b][i] = (att[b,:] @ M2[:,i]) * weight[b] + bias[b]
// Block tile 64 x 256, thread tile 8 rows x 8 cols.
// Accumulators are column-pairs (f32x2): B loads are natural pairs (no MOVs),
// A loads are warp-broadcast pre-duplicated pairs.
// ---------------------------------------------------------------------------
#define BM 64
#define BN 256
#define SM_ATT  (MD * BM * 2)            // floats (float2 per row)
#define SM_M2   (MD * BN)                // floats
#define SMEM_FLOATS (SM_ATT + SM_M2 + 2 * BM)
#define SMEM_BYTES  (SMEM_FLOATS * 4)

__global__ __launch_bounds__(256, 2) void k_gemm(float* __restrict__ out) {
    extern __shared__ float sm[];
    float2* att2 = (float2*)sm;                  // [MD][BM] duplicated pairs
    float*  m2s  = sm + SM_ATT;                  // [MD][BN]
    float*  wS   = m2s + SM_M2;                  // [BM]
    float*  biS  = wS + BM;                      // [BM]

    int tid  = threadIdx.x;
    int brow = blockIdx.y * BM;
    int bcol = blockIdx.x * BN;

    // Fill att tile: coalesced 8B loads, k-major global layout
    for (int i = tid; i < MD * BM; i += 256) {
        int k = i >> 6, r = i & 63;
        att2[i] = g_attT[(size_t)k * NB + brow + r];
    }
    // Fill M2 tile: coalesced float4
    for (int i4 = tid; i4 < MD * BN / 4; i4 += 256) {
        int k = i4 >> 6, c4 = i4 & 63;
        ((float4*)m2s)[i4] = *(const float4*)&g_M2[k * NL + bcol + c4 * 4];
    }
    if (tid < BM) {
        wS[tid]  = out[(size_t)NB * NL + brow + tid];
        biS[tid] = out[(size_t)NB * NL + NB + brow + tid];
    }
    __syncthreads();

    int tx = tid & 31, ty = tid >> 5;
    int r0 = ty * 8;            // 8 rows
    int c0 = tx * 8;            // 8 cols -> 4 f32x2 col-pairs

    unsigned long long acc[8][4];
#pragma unroll
    for (int r = 0; r < 8; r++)
#pragma unroll
        for (int p = 0; p < 4; p++) acc[r][p] = 0ull;

#pragma unroll 10
    for (int k = 0; k < MD; k++) {
        // A: 8 duplicated row-values, broadcast across the warp (all lanes same addr)
        const ulonglong2* ap = (const ulonglong2*)&att2[k * BM + r0];
        ulonglong2 A01 = ap[0], A23 = ap[1], A45 = ap[2], A67 = ap[3];
        // B: 4 natural column-pairs, contiguous 32B
        const ulonglong2* bp = (const ulonglong2*)&m2s[k * BN + c0];
        ulonglong2 B01 = bp[0], B23 = bp[1];

        fma2(acc[0][0], A01.x, B01.x); fma2(acc[0][1], A01.x, B01.y);
        fma2(acc[0][2], A01.x, B23.x); fma2(acc[0][3], A01.x, B23.y);
        fma2(acc[1][0], A01.y, B01.x); fma2(acc[1][1], A01.y, B01.y);
        fma2(acc[1][2], A01.y, B23.x); fma2(acc[1][3], A01.y, B23.y);
        fma2(acc[2][0], A23.x, B01.x); fma2(acc[2][1], A23.x, B01.y);
        fma2(acc[2][2], A23.x, B23.x); fma2(acc[2][3], A23.x, B23.y);
        fma2(acc[3][0], A23.y, B01.x); fma2(acc[3][1], A23.y, B01.y);
        fma2(acc[3][2], A23.y, B23.x); fma2(acc[3][3], A23.y, B23.y);
        fma2(acc[4][0], A45.x, B01.x); fma2(acc[4][1], A45.x, B01.y);
        fma2(acc[4][2], A45.x, B23.x); fma2(acc[4][3], A45.x, B23.y);
        fma2(acc[5][0], A45.y, B01.x); fma2(acc[5][1], A45.y, B01.y);
        fma2(acc[5][2], A45.y, B23.x); fma2(acc[5][3], A45.y, B23.y);
        fma2(acc[6][0], A67.x, B01.x); fma2(acc[6][1], A67.x, B01.y);
        fma2(acc[6][2], A67.x, B23.x); fma2(acc[6][3], A67.x, B23.y);
        fma2(acc[7][0], A67.y, B01.x); fma2(acc[7][1], A67.y, B01.y);
        fma2(acc[7][2], A67.y, B23.x); fma2(acc[7][3], A67.y, B23.y);
    }

    // Epilogue: *weight + bias, 2x STG.128 per row
#pragma unroll
    for (int r = 0; r < 8; r++) {
        int row = r0 + r;
        float w = wS[row], bv = biS[row];
        float2 u0 = unpk(acc[r][0]);
        float2 u1 = unpk(acc[r][1]);
        float2 u2 = unpk(acc[r][2]);
        float2 u3 = unpk(acc[r][3]);
        float4 v0, v1;
        v0.x = u0.x * w + bv; v0.y = u0.y * w + bv;
        v0.z = u1.x * w + bv; v0.w = u1.y * w + bv;
        v1.x = u2.x * w + bv; v1.y = u2.y * w + bv;
        v1.z = u3.x * w + bv; v1.w = u3.y * w + bv;
        float* o = out + (size_t)(brow + row) * NL + bcol + c0;
        *(float4*)o       = v0;
        *(float4*)(o + 4) = v1;
    }
}

// ---------------------------------------------------------------------------
extern "C" void kernel_launch(void* const* d_in, const int* in_sizes, int n_in,
                              void* d_out, int out_size) {
    const float* x        = (const float*)d_in[0];
    const float* date_vec = (const float*)d_in[1];
    // d_in[2] (conv_w) is dead code in the reference
    const float* convt_w  = (const float*)d_in[3];
    const float* mem_W    = (const float*)d_in[4];
    const float* date_W   = (const float*)d_in[5];
    const float* fcw_w    = (const float*)d_in[6];
    const float* fcw_b    = (const float*)d_in[7];
    const float* fcb_w    = (const float*)d_in[8];
    const float* fcb_b    = (const float*)d_in[9];
    float* out = (float*)d_out;

    cudaFuncSetAttribute(k_gemm, cudaFuncAttributeMaxDynamicSharedMemorySize,
                         SMEM_BYTES);

    k_prep_m2<<<(MD * NL + 255) / 256, 256>>>(mem_W, convt_w);
    k_att<<<NB / 128, 128>>>(date_vec, date_W);
    k_wb<<<NB / 8, 256>>>(x, fcw_w, fcw_b, fcb_w, fcb_b, out);
    dim3 g(NL / BN, NB / BM);
    k_gemm<<<g, 256, SMEM_BYTES>>>(out);
}